// round 3
// baseline (speedup 1.0000x reference)
#include <cuda_runtime.h>
#include <cuda_pipeline.h>
#include <cstdint>

// Problem constants
#define BATCH 8
#define CH    128          // CIN == COUT == 128
#define DIM   32
#define PLANE (DIM*DIM)        // 1024
#define VOL   (DIM*DIM*DIM)    // 32768
#define TAPS  27

// Scratch (no cudaMalloc allowed)
__device__ float g_wT[CH*CH*TAPS];   // [ic][oc][tap]
__device__ float g_demod[BATCH*CH];  // [b][oc]

// ---------------------------------------------------------------------------
// packed fp32 helpers (sm_100+ f32x2 path; ptxas never auto-fuses this)
// ---------------------------------------------------------------------------
__device__ __forceinline__ unsigned long long pk(float lo, float hi) {
    unsigned long long r;
    asm("mov.b64 %0, {%1, %2};" : "=l"(r) : "f"(lo), "f"(hi));
    return r;
}
__device__ __forceinline__ void upk(unsigned long long v, float& lo, float& hi) {
    asm("mov.b64 {%0, %1}, %2;" : "=f"(lo), "=f"(hi) : "l"(v));
}
#define FFMA2(d, a, b) \
    asm("fma.rn.f32x2 %0, %1, %2, %0;" : "+l"(d) : "l"(a), "l"(b))

// ---------------------------------------------------------------------------
// Kernel 1: transpose weights [O][I][27] -> [I][O][27] for coalesced per-ic reads
// ---------------------------------------------------------------------------
__global__ void wt_kernel(const float* __restrict__ w) {
    int idx = blockIdx.x * 256 + threadIdx.x;
    if (idx < CH*CH*TAPS) {
        int o = idx / (CH*TAPS);
        int r = idx - o * (CH*TAPS);
        int i = r / TAPS;
        int k = r - i * TAPS;
        g_wT[(i*CH + o)*TAPS + k] = w[idx];
    }
}

// ---------------------------------------------------------------------------
// Kernel 2: demod d[b,o] = rsqrt( sum_i (1+y[b,i])^2 * sum_k w[o,i,k]^2 + eps )
// grid: (128 o, 8 b), block: 128 threads (one per ic)
// ---------------------------------------------------------------------------
__global__ void demod_kernel(const float* __restrict__ y, const float* __restrict__ w) {
    int o = blockIdx.x, b = blockIdx.y, i = threadIdx.x;
    float s = 1.f + y[b*CH + i];
    const float* wp = w + (size_t)(o*CH + i) * TAPS;
    float a = 0.f;
    #pragma unroll
    for (int k = 0; k < TAPS; k++) { float v = wp[k]; a += v*v; }
    a *= s*s;
    __shared__ float red[CH];
    red[i] = a;
    __syncthreads();
    #pragma unroll
    for (int off = 64; off > 0; off >>= 1) {
        if (i < off) red[i] += red[i + off];
        __syncthreads();
    }
    if (i == 0) g_demod[b*CH + o] = rsqrtf(red[0] + 1e-8f);
}

// ---------------------------------------------------------------------------
// Kernel 3: shared-weight 3D conv, input-scale folded into weight tile,
// demod folded into stores. Block: 64 oc x (8 rows x 32 cols) at one (b, z).
// ---------------------------------------------------------------------------
#define XSW 34            // smem row width (cols -1..32) ; 136B rows keep LDS.64 aligned
#define XN  (3*10*XSW)    // 1020 elements per ic slab
#define WN  (64*TAPS)     // 1728 weights per ic per oc-half

__global__ void __launch_bounds__(256, 2)
conv_kernel(const float* __restrict__ x, const float* __restrict__ y,
            float* __restrict__ out) {
    __shared__ __align__(16) float xs[2][3][10][XSW];
    __shared__ float ws[2][WN];
    __shared__ float ysc[CH];

    const int tid = threadIdx.x;
    const int bx  = blockIdx.x;            // 0..7
    const int z   = blockIdx.y;            // 0..31
    const int b   = blockIdx.z;            // 0..7
    const int oc_base  = (bx & 1) * 64;
    const int row_base = (bx >> 1) * 8;

    if (tid < CH) ysc[tid] = 1.f + y[b*CH + tid];
    __syncthreads();

    const int ocg = tid >> 5;              // warp id = oc group (weight LDS broadcasts)
    const int spg = tid & 31;
    const int lr  = spg >> 2;              // local row 0..7
    const int cb  = (spg & 3) * 8;         // col base 0/8/16/24

    const float* xb = x + (size_t)b * CH * VOL;

    auto prefetch_x = [&](int ic, int buf) {
        const float* xc = xb + (size_t)ic * VOL;
        for (int t = tid; t < XN; t += 256) {
            int p  = t / (10*XSW);
            int r2 = t - p * (10*XSW);
            int r  = r2 / XSW;
            int c  = r2 - r * XSW;
            int gz = z - 1 + p;
            int gy = row_base - 1 + r;
            int gx = c - 1;
            bool ok = ((unsigned)gz < (unsigned)DIM) &
                      ((unsigned)gy < (unsigned)DIM) &
                      ((unsigned)gx < (unsigned)DIM);
            const float* src = ok ? (xc + gz*PLANE + gy*DIM + gx) : xc;
            __pipeline_memcpy_async(&xs[buf][p][r][c], src, 4, ok ? 0 : 4);
        }
    };

    float wreg[7];
    auto ldg_w = [&](int ic) {
        const float* wp = g_wT + ((size_t)ic * CH + oc_base) * TAPS;
        #pragma unroll
        for (int j = 0; j < 7; j++) {
            int t = tid + j * 256;
            wreg[j] = (t < WN) ? wp[t] : 0.f;
        }
    };
    auto sts_w = [&](int ic, int buf) {
        float s = ysc[ic];
        #pragma unroll
        for (int j = 0; j < 7; j++) {
            int t = tid + j * 256;
            if (t < WN) ws[buf][t] = wreg[j] * s;
        }
    };

    unsigned long long acc[8][4];
    #pragma unroll
    for (int u = 0; u < 8; u++)
        #pragma unroll
        for (int p = 0; p < 4; p++) acc[u][p] = 0ull;

    // prologue: stage ic=0
    ldg_w(0);
    prefetch_x(0, 0);
    __pipeline_commit();
    sts_w(0, 0);

    for (int ic = 0; ic < CH; ++ic) {
        const int cur = ic & 1, nxt = cur ^ 1;
        __pipeline_wait_prior(0);
        __syncthreads();                       // cur data ready; nxt buffer free

        if (ic + 1 < CH) {
            ldg_w(ic + 1);                     // global loads issued early
            prefetch_x(ic + 1, nxt);
            __pipeline_commit();
        }

        const float* wsc = ws[cur];
        for (int dz = 0; dz < 3; ++dz) {
            #pragma unroll
            for (int dy = 0; dy < 3; ++dy) {
                const float* xrow = &xs[cur][dz][lr + dy][cb];
                unsigned long long e[5];
                #pragma unroll
                for (int m = 0; m < 5; m++)
                    e[m] = *(const unsigned long long*)(xrow + 2*m);
                unsigned long long xp[9];
                #pragma unroll
                for (int m = 0; m < 5; m++) xp[2*m] = e[m];
                #pragma unroll
                for (int m = 0; m < 4; m++) {
                    float l0, h0, l1, h1;
                    upk(e[m],   l0, h0);
                    upk(e[m+1], l1, h1);
                    xp[2*m + 1] = pk(h0, l1);
                }
                const int tb = dz*9 + dy*3;
                #pragma unroll
                for (int u = 0; u < 8; ++u) {
                    const float* wp = wsc + (ocg*8 + u)*TAPS + tb;   // broadcast LDS
                    unsigned long long w0 = pk(wp[0], wp[0]);
                    unsigned long long w1 = pk(wp[1], wp[1]);
                    unsigned long long w2 = pk(wp[2], wp[2]);
                    #pragma unroll
                    for (int p = 0; p < 4; ++p) {
                        FFMA2(acc[u][p], w0, xp[2*p]);
                        FFMA2(acc[u][p], w1, xp[2*p + 1]);
                        FFMA2(acc[u][p], w2, xp[2*p + 2]);
                    }
                }
            }
        }

        if (ic + 1 < CH) sts_w(ic + 1, nxt);   // LDGs long since landed; no stall
    }

    // epilogue: demod + float4 stores
    const float* dm = g_demod + b*CH + oc_base + ocg*8;
    float* ob = out + (((size_t)b*CH + oc_base + ocg*8) * DIM + z) * PLANE
                    + (row_base + lr) * DIM + cb;
    #pragma unroll
    for (int u = 0; u < 8; ++u) {
        float d = dm[u];
        float a0, a1;
        float4 v0, v1;
        upk(acc[u][0], a0, a1); v0.x = a0*d; v0.y = a1*d;
        upk(acc[u][1], a0, a1); v0.z = a0*d; v0.w = a1*d;
        upk(acc[u][2], a0, a1); v1.x = a0*d; v1.y = a1*d;
        upk(acc[u][3], a0, a1); v1.z = a0*d; v1.w = a1*d;
        float* op = ob + (size_t)u * DIM * PLANE;
        *(float4*)(op)     = v0;
        *(float4*)(op + 4) = v1;
    }
}

// ---------------------------------------------------------------------------
// launch: inputs are x [8,128,32,32,32] f32, y [8,128] f32, weight [128,128,27] f32
// ---------------------------------------------------------------------------
extern "C" void kernel_launch(void* const* d_in, const int* in_sizes, int n_in,
                              void* d_out, int out_size) {
    const float* x = (const float*)d_in[0];
    const float* y = (const float*)d_in[1];
    const float* w = (const float*)d_in[2];
    float* out = (float*)d_out;

    wt_kernel<<<(CH*CH*TAPS + 255) / 256, 256>>>(w);
    demod_kernel<<<dim3(CH, BATCH), CH>>>(y, w);
    conv_kernel<<<dim3(8, DIM, BATCH), 256>>>(x, y, out);
}

// round 6
// speedup vs baseline: 3.0587x; 3.0587x over previous
#include <cuda_runtime.h>
#include <cstdint>

#define CH 128
#define BATCH 8
#define DIM 32
#define PLANE 1024
#define VOL 32768
#define APAD 132

__device__ __align__(16) float g_xs[(size_t)BATCH*VOL*CH];  // [b][z][y][x][ic'] scaled tf32
__device__ __align__(16) float g_wt[27*CH*CH];              // [tap][oc][ic'] tf32
__device__ float g_dm[BATCH*CH];

__device__ __forceinline__ float tf32r(float v){
    uint32_t u; asm("cvt.rna.tf32.f32 %0, %1;":"=r"(u):"f"(v));
    return __uint_as_float(u);
}
__device__ __forceinline__ int perm8(int i){
    return (i & ~7) | (((i & 3) << 1) | ((i >> 2) & 1));
}
__device__ __forceinline__ uint32_t s2u(const void* p){
    uint32_t a;
    asm("{ .reg .u64 t; cvta.to.shared.u64 t, %1; cvt.u32.u64 %0, t; }":"=r"(a):"l"(p));
    return a;
}
__device__ __forceinline__ void cpa16(uint32_t d, const void* s, bool ok){
    if(ok) asm volatile("cp.async.cg.shared.global [%0],[%1],16;"::"r"(d),"l"(s):"memory");
    else   asm volatile("cp.async.cg.shared.global [%0],[%1],16,0;"::"r"(d),"l"(s):"memory");
}
#define CPCOMMIT() asm volatile("cp.async.commit_group;":::"memory")
#define CPWAIT(n)  asm volatile("cp.async.wait_group %0;"::"n"(n):"memory")
#define MMA(c, a0,a1,a2,a3, b0,b1) \
    asm volatile("mma.sync.aligned.m16n8k8.row.col.f32.tf32.tf32.f32 " \
        "{%0,%1,%2,%3}, {%4,%5,%6,%7}, {%8,%9}, {%0,%1,%2,%3};" \
        : "+f"((c)[0]),"+f"((c)[1]),"+f"((c)[2]),"+f"((c)[3]) \
        : "r"(a0),"r"(a1),"r"(a2),"r"(a3),"r"(b0),"r"(b1))

// ---- prep: weights [o][i][27] -> g_wt[tap][o][perm8(i)], tf32 ----
__global__ void wprep(const float* __restrict__ w){
    int id = blockIdx.x*256 + threadIdx.x;
    if(id >= 27*CH*CH) return;
    int t = id / (CH*CH), r = id % (CH*CH), o = r >> 7, i = r & 127;
    g_wt[(size_t)t*16384 + o*128 + perm8(i)] = tf32r(w[(size_t)(o*128+i)*27 + t]);
}
// ---- prep: x -> scaled tf32, slot-major [b,z,y,x][perm8(ic)] ----
__global__ void xprep(const float* __restrict__ x, const float* __restrict__ ym){
    __shared__ float t[128][33];
    int b = blockIdx.z, z = blockIdx.y, yy = blockIdx.x;
    const float* xp = x + (size_t)b*CH*VOL + z*PLANE + yy*DIM;
    for(int r=0;r<16;r++){ int idx=r*256+threadIdx.x; int i=idx>>5, xx=idx&31;
        t[i][xx] = tf32r((1.f+ym[b*CH+i]) * xp[(size_t)i*VOL+xx]); }
    __syncthreads();
    float* op = g_xs + (size_t)(((b*DIM+z)*DIM+yy)*DIM)*CH;
    for(int r=0;r<16;r++){ int idx=r*256+threadIdx.x; int xx=idx>>7, i=idx&127;
        op[(size_t)xx*CH + perm8(i)] = t[i][xx]; }
}
// ---- prep: demod (fp32 exact) ----
__global__ void demod(const float* __restrict__ ym, const float* __restrict__ w){
    int o = blockIdx.x, b = blockIdx.y, i = threadIdx.x;
    float s = 1.f + ym[b*CH+i];
    const float* wp = w + (size_t)(o*128+i)*27;
    float a = 0.f;
    #pragma unroll
    for(int k=0;k<27;k++){ float v = wp[k]; a += v*v; }
    a *= s*s;
    __shared__ float red[128];
    red[i] = a; __syncthreads();
    #pragma unroll
    for(int off=64; off>0; off>>=1){ if(i<off) red[i]+=red[i+off]; __syncthreads(); }
    if(i==0) g_dm[b*CH+o] = rsqrtf(red[0] + 1e-8f);
}

// ---- conv: mma.sync tf32 implicit GEMM ----
// smem floats: A[4*34*132]=17952 @0 ; B0 @17952 ; B1 @34848 ; total 51744 f = 206976 B
#define AOFF 0
#define B0OFF 17952
#define BSZ   16896
#define DYNSM 206976
__global__ void __launch_bounds__(256,1) conv(float* __restrict__ out){
    extern __shared__ __align__(16) float sf[];
    const uint32_t S = s2u(sf);
    const int tid = threadIdx.x;
    const int rb = blockIdx.x, z = blockIdx.y, b = blockIdx.z;
    const int r0 = rb*4;
    const int wid = tid>>5, l = tid&31;
    const int wm = wid&1, wn = wid>>1;
    const int g4 = l>>2, t4 = l&3;

    auto stageA = [&](int g){
        int dz = g/3, dy = g%3;
        int zz = z + dz - 1;
        bool zok = (unsigned)zz < 32u;
        const float* base = g_xs + ((size_t)(b*DIM + (zok?zz:0)) * PLANE) * CH;
        for(int c=tid; c<4352; c+=256){
            int slot = c>>5, part = c&31;
            int jr = slot/34, xi = slot - jr*34;
            int yy = r0 + jr + dy - 1, xx = xi - 1;
            bool ok = zok && ((unsigned)yy < 32u) && ((unsigned)xx < 32u);
            const float* src = base + (size_t)((ok?yy:0)*DIM + (ok?xx:0))*CH + part*4;
            cpa16(S + (uint32_t)(slot*APAD + part*4)*4, src, ok);
        }
    };
    auto stageB = [&](int t, int buf){
        const float* src = g_wt + (size_t)t*16384;
        uint32_t dst = S + (uint32_t)(B0OFF + buf*BSZ)*4;
        for(int c=tid; c<4096; c+=256){
            int o = c>>5, part = c&31;
            cpa16(dst + (uint32_t)(o*APAD + part*4)*4, src + o*128 + part*4, true);
        }
    };

    // per-lane fragment bases
    int arow[4], boff[4];
    #pragma unroll
    for(int mi=0;mi<4;mi++){
        int mb = wm*64 + mi*16;
        arow[mi] = (mb>>5)*34 + (mb&31) + g4;     // + dx at use
    }
    #pragma unroll
    for(int ni=0;ni<4;ni++)
        boff[ni] = (wn*32 + ni*8 + g4)*APAD + 2*t4;

    float acc[4][4][4];
    #pragma unroll
    for(int mi=0;mi<4;mi++)
        #pragma unroll
        for(int ni=0;ni<4;ni++)
            #pragma unroll
            for(int e=0;e<4;e++) acc[mi][ni][e] = 0.f;

    // prologue
    stageA(0); CPCOMMIT();
    stageB(0,0); CPCOMMIT();
    stageB(1,1); CPCOMMIT();
    CPWAIT(1); __syncthreads();          // A0,B0 ready

    for(int t=0; t<27; t++){
        const int g = t/3, dx = t - g*3, buf = t&1;
        const float* B = sf + B0OFF + buf*BSZ;
        const float* A = sf + AOFF;
        #pragma unroll
        for(int kb=0; kb<16; kb++){
            uint2 bf[4];
            #pragma unroll
            for(int ni=0;ni<4;ni++)
                bf[ni] = *(const uint2*)(B + boff[ni] + kb*8);
            #pragma unroll
            for(int mi=0;mi<4;mi++){
                const float* ap = A + (arow[mi]+dx)*APAD + kb*8 + 2*t4;
                uint2 alo = *(const uint2*)ap;
                uint2 ahi = *(const uint2*)(ap + 8*APAD);
                #pragma unroll
                for(int ni=0;ni<4;ni++)
                    MMA(acc[mi][ni], alo.x, ahi.x, alo.y, ahi.y, bf[ni].x, bf[ni].y);
            }
        }
        if(t == 26) break;
        __syncthreads();                               // done reading Bbuf[buf] (and A at grp end)
        if(dx == 2 && g+1 < 9){ stageA(g+1); CPCOMMIT(); }
        if(t+2 < 27){ stageB(t+2, buf); CPCOMMIT(); }
        if(t+2 < 27){ CPWAIT(1); } else { CPWAIT(0); } // retire B_{t+1} (+A_{g+1})
        __syncthreads();
    }

    // epilogue: frags -> smem [oc][APAD] over A region, then demod + coalesced store
    __syncthreads();
    float* Cs = sf;   // 128*132 = 16896 floats <= 17952
    #pragma unroll
    for(int mi=0;mi<4;mi++){
        int mb = wm*64 + mi*16;
        #pragma unroll
        for(int ni=0;ni<4;ni++){
            int nb = wn*32 + ni*8 + 2*t4;
            Cs[(nb  )*APAD + mb + g4    ] = acc[mi][ni][0];
            Cs[(nb+1)*APAD + mb + g4    ] = acc[mi][ni][1];
            Cs[(nb  )*APAD + mb + g4 + 8] = acc[mi][ni][2];
            Cs[(nb+1)*APAD + mb + g4 + 8] = acc[mi][ni][3];
        }
    }
    __syncthreads();
    {
        int oc = tid>>1, half = tid&1;
        float d = g_dm[b*CH + oc];
        float* op = out + ((size_t)b*CH + oc)*VOL + z*PLANE + r0*32 + half*64;
        const float* cr = Cs + oc*APAD + half*64;
        #pragma unroll
        for(int j=0;j<16;j++){
            float4 v = *(const float4*)(cr + j*4);
            v.x *= d; v.y *= d; v.z *= d; v.w *= d;
            *(float4*)(op + j*4) = v;
        }
    }
}

extern "C" void kernel_launch(void* const* d_in, const int* in_sizes, int n_in,
                              void* d_out, int out_size){
    const float* x = (const float*)d_in[0];
    const float* y = (const float*)d_in[1];
    const float* w = (const float*)d_in[2];
    float* out = (float*)d_out;
    cudaFuncSetAttribute(conv, cudaFuncAttributeMaxDynamicSharedMemorySize, DYNSM);
    wprep<<<(27*CH*CH + 255)/256, 256>>>(w);
    xprep<<<dim3(32,32,8), 256>>>(x, y);
    demod<<<dim3(128,8), 128>>>(y, w);
    conv<<<dim3(8,32,8), 256, DYNSM>>>(out);
}